// round 3
// baseline (speedup 1.0000x reference)
#include <cuda_runtime.h>
#include <math.h>
#include <stdint.h>

#define B_IMG   32
#define NBOX    50
#define NCLS    20
#define A_TOT   10647
#define NUM_NEG 1000
#define EPSF    1e-7f
#define FOURPI2 0.4052847345693511f   // 4/pi^2

// ---- scratch (no allocations allowed) ----
__device__ float    g_pos[B_IMG];
__device__ float    g_neg[B_IMG];
__device__ uint32_t g_keys[B_IMG * A_TOT];

__constant__ float c_asc[9][2] = {
    {10.f/416.f,13.f/416.f},{16.f/416.f,30.f/416.f},{33.f/416.f,23.f/416.f},
    {30.f/416.f,61.f/416.f},{62.f/416.f,45.f/416.f},{59.f/416.f,119.f/416.f},
    {116.f/416.f,90.f/416.f},{156.f/416.f,198.f/416.f},{373.f/416.f,326.f/416.f}};
__constant__ float c_fs9[9] = {52.f,52.f,52.f,26.f,26.f,26.f,13.f,13.f,13.f};

// ---- math helpers (match JAX f32 formulas to ~ulp) ----
__device__ __forceinline__ float softplusf(float x) {
    return fmaxf(x, 0.f) + log1pf(expf(-fabsf(x)));
}
__device__ __forceinline__ float sigm(float x) { return 1.f / (1.f + expf(-x)); }
// focal(x, t=0): bce(x,0)*(1-ALPHA)*pr^2
__device__ __forceinline__ float focal0(float x) {
    float pr = sigm(x);
    return softplusf(x) * 0.75f * pr * pr;
}
// focal(x, t=1): bce(x,1)*ALPHA*(1-pr)^2
__device__ __forceinline__ float focal1(float x) {
    float pr = sigm(x); float q = 1.f - pr;
    return softplusf(-x) * 0.25f * q * q;
}
// bce with logits for t in {0,1}
__device__ __forceinline__ float bce01(float x, bool t1) {
    return t1 ? softplusf(-x) : softplusf(x);
}

// CIoU on two ltrb boxes (matches reference formula incl. eps placement)
__device__ __forceinline__ float ciouf(float l1, float t1, float r1, float b1,
                                       float l2, float t2, float r2, float b2) {
    float iw = fminf(r1, r2) - fmaxf(l1, l2); iw = fmaxf(iw, 0.f);
    float ih = fminf(b1, b2) - fmaxf(t1, t2); ih = fmaxf(ih, 0.f);
    float inter = iw * ih;
    float w1 = r1 - l1, h1 = b1 - t1;
    float w2 = r2 - l2, h2 = b2 - t2;
    float uni = w1 * h1 + w2 * h2 - inter + EPSF;
    float iou = inter / uni;
    float cw = fmaxf(r1, r2) - fminf(l1, l2);
    float ch = fmaxf(b1, b2) - fminf(t1, t2);
    float c2 = cw * cw + ch * ch + EPSF;
    float dx = (l1 + r1) - (l2 + r2);
    float dy = (t1 + b1) - (t2 + b2);
    float rho2 = 0.25f * (dx * dx + dy * dy);
    float dv = atanf(w1 / (h1 + EPSF)) - atanf(w2 / (h2 + EPSF));
    float v = FOURPI2 * dv * dv;
    float al = v / (1.f - iou + v + EPSF);
    return iou - rho2 / c2 - al * v;
}

// =====================================================================
// Kernel 1: anchor matching (exact offset-trick argmax over nb*9=450
// candidates, first-max tie rule) + positive losses. One block per image.
// =====================================================================
__global__ void __launch_bounds__(512)
k_match_pos(const float* __restrict__ p, const float* __restrict__ boxes,
            const int* __restrict__ labels, const float* __restrict__ ancs)
{
    const int b = blockIdx.x;
    __shared__ float sbx[NBOX][4];
    __shared__ int   slb[NBOX];
    __shared__ float wsum[16];

    const int tid = threadIdx.x, warp = tid >> 5, lane = tid & 31;
    for (int i = tid; i < NBOX * 4; i += blockDim.x)
        (&sbx[0][0])[i] = boxes[b * NBOX * 4 + i];
    for (int i = tid; i < NBOX; i += blockDim.x)
        slb[i] = labels[b * NBOX + i];
    __syncthreads();

    const float* pb = p + (size_t)b * A_TOT * 25;
    float wacc = 0.f;

    for (int i = warp; i < NBOX; i += 16) {
        const float l1 = sbx[i][0], t1 = sbx[i][1], r1 = sbx[i][2], bb1 = sbx[i][3];
        const float off = (float)i;

        // --- argmax over 450 candidates (column index c = j*9+m) ---
        float best = -1e30f; int bestc = 1 << 30;
        for (int c = lane; c < NBOX * 9; c += 32) {
            int j = c / 9, m = c - j * 9;
            float fs = c_fs9[m];
            float cx = (sbx[j][0] + sbx[j][2]) * 0.5f * fs;
            float cy = (sbx[j][1] + sbx[j][3]) * 0.5f * fs;
            float ax = floorf(cx) / fs, ay = floorf(cy) / fs;
            float aw = c_asc[m][0], ah = c_asc[m][1];
            float jo = (float)j;
            float al = ax - aw * 0.5f + jo, at = ay - ah * 0.5f + jo;
            float ar = ax + aw * 0.5f + jo, ab = ay + ah * 0.5f + jo;
            float v = ciouf(l1 + off, t1 + off, r1 + off, bb1 + off, al, at, ar, ab);
            if (v > best || (v == best && c < bestc)) { best = v; bestc = c; }
        }
        for (int o = 16; o > 0; o >>= 1) {
            float v2 = __shfl_down_sync(0xffffffffu, best, o);
            int   i2 = __shfl_down_sync(0xffffffffu, bestc, o);
            if (v2 > best || (v2 == best && i2 < bestc)) { best = v2; bestc = i2; }
        }
        bestc = __shfl_sync(0xffffffffu, bestc, 0);

        const int k = bestc % 9, level = k / 3;
        const float fs = c_fs9[k];
        const int col = (int)floorf((l1 + r1) * 0.5f * fs);
        const int row = (int)floorf((t1 + bb1) * 0.5f * fs);
        const int fsl = (level == 0) ? 52 : ((level == 1) ? 26 : 13);
        const int cum = (level == 0) ? 0 : ((level == 1) ? 2704 : 3380);
        // NOTE: reference adds +level (not k%3) — replicate exactly.
        const int midx = (cum + row * fsl + col) * 3 + level;
        const float* pm = pb + (size_t)midx * 25;

        float contrib = 0.f;
        if (lane < NCLS) {
            contrib = bce01(pm[5 + lane], (slb[i] - 1) == lane);
        } else if (lane == NCLS) {
            contrib = focal1(pm[4]);
        } else if (lane == NCLS + 1) {
            float fa = (float)fsl;
            float acx = ancs[midx * 4 + 0], acy = ancs[midx * 4 + 1];
            float aw  = ancs[midx * 4 + 2], ah  = ancs[midx * 4 + 3];
            float px = sigm(pm[0]) / fa + acx;
            float py = sigm(pm[1]) / fa + acy;
            float pw = expf(pm[2]) * aw;
            float ph = expf(pm[3]) * ah;
            float iou1 = ciouf(l1, t1, r1, bb1,
                               px - pw * 0.5f, py - ph * 0.5f,
                               px + pw * 0.5f, py + ph * 0.5f);
            float gw = r1 - l1, gh = bb1 - t1;
            contrib = (2.f - gw * gh) * (1.f - iou1);
        }
        for (int o = 16; o > 0; o >>= 1)
            contrib += __shfl_down_sync(0xffffffffu, contrib, o);
        if (lane == 0) wacc += contrib;
    }
    if (lane == 0) wsum[warp] = wacc;
    __syncthreads();
    if (tid == 0) {
        float s = 0.f;
        for (int w = 0; w < 16; w++) s += wsum[w];
        g_pos[b] = s;   // l_cls + l_iou + l_conf_pos (undivided)
    }
}

// =====================================================================
// Kernel 2: per-anchor OHEM key. Thread = (image, anchor): decode pred,
// max CIoU vs 50 GT boxes, masked -> order-preserving uint32.
// =====================================================================
__global__ void __launch_bounds__(256)
k_neg_keys(const float* __restrict__ p, const float* __restrict__ boxes,
           const float* __restrict__ ancs)
{
    const int b = blockIdx.y;
    const int a = blockIdx.x * blockDim.x + threadIdx.x;

    __shared__ float sb[NBOX][8]; // l,t,r,b, s_x, s_y, area, atanv
    if (threadIdx.x < NBOX) {
        const float* bp = boxes + (size_t)(b * NBOX + threadIdx.x) * 4;
        float l = bp[0], t = bp[1], r = bp[2], bb = bp[3];
        sb[threadIdx.x][0] = l;  sb[threadIdx.x][1] = t;
        sb[threadIdx.x][2] = r;  sb[threadIdx.x][3] = bb;
        sb[threadIdx.x][4] = l + r;
        sb[threadIdx.x][5] = t + bb;
        sb[threadIdx.x][6] = (r - l) * (bb - t);
        sb[threadIdx.x][7] = atanf((r - l) / ((bb - t) + EPSF));
    }
    __syncthreads();
    if (a >= A_TOT) return;

    const float* pp = p + ((size_t)b * A_TOT + a) * 25;
    const int level = (a < 8112) ? 0 : ((a < 10140) ? 1 : 2);
    const float fa = (level == 0) ? 52.f : ((level == 1) ? 26.f : 13.f);
    float px = sigm(pp[0]) / fa + ancs[a * 4 + 0];
    float py = sigm(pp[1]) / fa + ancs[a * 4 + 1];
    float pw = expf(pp[2]) * ancs[a * 4 + 2];
    float ph = expf(pp[3]) * ancs[a * 4 + 3];
    float l1 = px - pw * 0.5f, t1 = py - ph * 0.5f;
    float r1 = px + pw * 0.5f, b1 = py + ph * 0.5f;
    float area1 = pw * ph;
    float atan1 = atanf(pw / (ph + EPSF));
    float s1x = l1 + r1, s1y = t1 + b1;

    float mx = -1e30f;
    #pragma unroll 5
    for (int j = 0; j < NBOX; j++) {
        float l2 = sb[j][0], t2 = sb[j][1], r2 = sb[j][2], b2 = sb[j][3];
        float iw = fminf(r1, r2) - fmaxf(l1, l2); iw = fmaxf(iw, 0.f);
        float ih = fminf(b1, b2) - fmaxf(t1, t2); ih = fmaxf(ih, 0.f);
        float inter = iw * ih;
        float uni = area1 + sb[j][6] - inter + EPSF;
        float iou = inter / uni;
        float cw = fmaxf(r1, r2) - fminf(l1, l2);
        float ch = fmaxf(b1, b2) - fminf(t1, t2);
        float c2 = cw * cw + ch * ch + EPSF;
        float dx = s1x - sb[j][4], dy = s1y - sb[j][5];
        float rho2 = 0.25f * (dx * dx + dy * dy);
        float dv = sb[j][7] - atan1;   // symmetric in square
        float v = FOURPI2 * dv * dv;
        float al = v / (1.f - iou + v + EPSF);
        float ci = iou - rho2 / c2 - al * v;
        mx = fmaxf(mx, ci);
    }
    float masked = (mx < 0.5f) ? mx : __int_as_float(0x7f800000); // +inf
    uint32_t u = __float_as_uint(masked);
    uint32_t key = (u & 0x80000000u) ? ~u : (u | 0x80000000u);
    g_keys[b * A_TOT + a] = key;
}

// =====================================================================
// Kernel 3: per-image radix-select of the 1000 smallest keys (exact
// top_k tie semantics: equal value -> lower index) + sum focal(conf,0).
// One block per image, keys resident in shared memory.
// =====================================================================
__global__ void __launch_bounds__(256)
k_select_neg(const float* __restrict__ p)
{
    const int b = blockIdx.x;
    __shared__ uint32_t sk[A_TOT];
    __shared__ unsigned int hist[256];
    __shared__ uint32_t s_prefix;
    __shared__ int s_k;
    __shared__ float red[256];

    const int tid = threadIdx.x, NT = 256;
    for (int i = tid; i < A_TOT; i += NT) sk[i] = g_keys[b * A_TOT + i];
    if (tid == 0) { s_prefix = 0u; s_k = NUM_NEG; }
    __syncthreads();

    for (int pass = 0; pass < 4; pass++) {
        const int shift = 24 - 8 * pass;
        const uint32_t himask = (pass == 0) ? 0u : (0xFFFFFFFFu << (shift + 8));
        hist[tid] = 0u;
        __syncthreads();
        const uint32_t pref = s_prefix;
        for (int i = tid; i < A_TOT; i += NT) {
            uint32_t key = sk[i];
            if ((key & himask) == pref)
                atomicAdd(&hist[(key >> shift) & 255u], 1u);
        }
        __syncthreads();
        if (tid == 0) {
            int k = s_k, cum = 0, d = 0;
            for (; d < 255; d++) {
                if (cum + (int)hist[d] >= k) break;
                cum += (int)hist[d];
            }
            s_prefix = pref | ((uint32_t)d << shift);
            s_k = k - cum;
        }
        __syncthreads();
    }
    const uint32_t V = s_prefix;
    const int kRem = s_k;

    float part = 0.f;
    for (int i = tid; i < A_TOT; i += NT) {
        uint32_t key = sk[i];
        bool take = false;
        if (key < V) take = true;
        else if (key == V) {
            int rank = 0;
            for (int j = 0; j < i; j++) rank += (sk[j] == V);
            take = (rank < kRem);
        }
        if (take) part += focal0(p[((size_t)b * A_TOT + i) * 25 + 4]);
    }
    red[tid] = part;
    __syncthreads();
    for (int s = 128; s > 0; s >>= 1) {
        if (tid < s) red[tid] += red[tid + s];
        __syncthreads();
    }
    if (tid == 0) g_neg[b] = red[0];
}

// =====================================================================
// Kernel 4: combine -> scalar. out = mean_b( pos_b/50 + neg_b )
// =====================================================================
__global__ void k_final(float* __restrict__ out)
{
    if (threadIdx.x == 0 && blockIdx.x == 0) {
        float s = 0.f;
        for (int b = 0; b < B_IMG; b++)
            s += g_pos[b] * (1.f / (float)NBOX) + g_neg[b];
        out[0] = s * (1.f / (float)B_IMG);
    }
}

extern "C" void kernel_launch(void* const* d_in, const int* in_sizes, int n_in,
                              void* d_out, int out_size)
{
    const float* p      = (const float*)d_in[0];   // [32,10647,25]
    const float* boxes  = (const float*)d_in[1];   // [32,50,4] ltrb
    const int*   labels = (const int*)d_in[2];     // [32,50]
    const float* ancs   = (const float*)d_in[3];   // [10647,4] xywh
    float* out = (float*)d_out;

    k_match_pos<<<B_IMG, 512>>>(p, boxes, labels, ancs);

    dim3 gB((A_TOT + 255) / 256, B_IMG);
    k_neg_keys<<<gB, 256>>>(p, boxes, ancs);

    k_select_neg<<<B_IMG, 256>>>(p);

    k_final<<<1, 32>>>(out);
}

// round 7
// speedup vs baseline: 1.8880x; 1.8880x over previous
#include <cuda_runtime.h>
#include <math.h>
#include <stdint.h>

#define B_IMG   32
#define NBOX    50
#define NCLS    20
#define A_TOT   10647
#define NUM_NEG 1000
#define EPSF    1e-7f
#define FOURPI2 0.4052847345693511f   // 4/pi^2

// ---- scratch (no allocations allowed) ----
__device__ float    g_pos[B_IMG];
__device__ float    g_neg[B_IMG];
__device__ uint32_t g_keys[B_IMG * A_TOT];

__constant__ float c_asc[9][2] = {
    {10.f/416.f,13.f/416.f},{16.f/416.f,30.f/416.f},{33.f/416.f,23.f/416.f},
    {30.f/416.f,61.f/416.f},{62.f/416.f,45.f/416.f},{59.f/416.f,119.f/416.f},
    {116.f/416.f,90.f/416.f},{156.f/416.f,198.f/416.f},{373.f/416.f,326.f/416.f}};
__constant__ float c_fs9[9] = {52.f,52.f,52.f,26.f,26.f,26.f,13.f,13.f,13.f};

// ---- precise math helpers (value-bearing paths) ----
__device__ __forceinline__ float softplusf(float x) {
    return fmaxf(x, 0.f) + log1pf(expf(-fabsf(x)));
}
__device__ __forceinline__ float sigm(float x) { return 1.f / (1.f + expf(-x)); }
__device__ __forceinline__ float focal0(float x) {           // focal(x, t=0)
    float pr = sigm(x);
    return softplusf(x) * 0.75f * pr * pr;
}
__device__ __forceinline__ float focal1(float x) {           // focal(x, t=1)
    float pr = sigm(x); float q = 1.f - pr;
    return softplusf(-x) * 0.25f * q * q;
}
__device__ __forceinline__ float bce01(float x, bool t1) {
    return t1 ? softplusf(-x) : softplusf(x);
}

// Full-precision CIoU on two ltrb boxes (matches reference formula)
__device__ __forceinline__ float ciouf(float l1, float t1, float r1, float b1,
                                       float l2, float t2, float r2, float b2) {
    float iw = fminf(r1, r2) - fmaxf(l1, l2); iw = fmaxf(iw, 0.f);
    float ih = fminf(b1, b2) - fmaxf(t1, t2); ih = fmaxf(ih, 0.f);
    float inter = iw * ih;
    float w1 = r1 - l1, h1 = b1 - t1;
    float w2 = r2 - l2, h2 = b2 - t2;
    float uni = w1 * h1 + w2 * h2 - inter + EPSF;
    float iou = inter / uni;
    float cw = fmaxf(r1, r2) - fminf(l1, l2);
    float ch = fmaxf(b1, b2) - fminf(t1, t2);
    float c2 = cw * cw + ch * ch + EPSF;
    float dx = (l1 + r1) - (l2 + r2);
    float dy = (t1 + b1) - (t2 + b2);
    float rho2 = 0.25f * (dx * dx + dy * dy);
    float dv = atanf(w1 / (h1 + EPSF)) - atanf(w2 / (h2 + EPSF));
    float v = FOURPI2 * dv * dv;
    float al = v / (1.f - iou + v + EPSF);
    return iou - rho2 / c2 - al * v;
}

// =====================================================================
// Kernel 1: anchor matching (exact offset-trick argmax, full precision)
// + positive losses. One block per image.
// =====================================================================
__global__ void __launch_bounds__(512)
k_match_pos(const float* __restrict__ p, const float* __restrict__ boxes,
            const int* __restrict__ labels, const float* __restrict__ ancs)
{
    const int b = blockIdx.x;
    __shared__ float sbx[NBOX][4];
    __shared__ int   slb[NBOX];
    __shared__ float wsum[16];

    const int tid = threadIdx.x, warp = tid >> 5, lane = tid & 31;
    for (int i = tid; i < NBOX * 4; i += blockDim.x)
        (&sbx[0][0])[i] = boxes[b * NBOX * 4 + i];
    for (int i = tid; i < NBOX; i += blockDim.x)
        slb[i] = labels[b * NBOX + i];
    __syncthreads();

    const float* pb = p + (size_t)b * A_TOT * 25;
    float wacc = 0.f;

    for (int i = warp; i < NBOX; i += 16) {
        const float l1 = sbx[i][0], t1 = sbx[i][1], r1 = sbx[i][2], bb1 = sbx[i][3];
        const float off = (float)i;

        float best = -1e30f; int bestc = 1 << 30;
        for (int c = lane; c < NBOX * 9; c += 32) {
            int j = c / 9, m = c - j * 9;
            float fs = c_fs9[m];
            float cx = (sbx[j][0] + sbx[j][2]) * 0.5f * fs;
            float cy = (sbx[j][1] + sbx[j][3]) * 0.5f * fs;
            float ax = floorf(cx) / fs, ay = floorf(cy) / fs;
            float aw = c_asc[m][0], ah = c_asc[m][1];
            float jo = (float)j;
            float al = ax - aw * 0.5f + jo, at = ay - ah * 0.5f + jo;
            float ar = ax + aw * 0.5f + jo, ab = ay + ah * 0.5f + jo;
            float v = ciouf(l1 + off, t1 + off, r1 + off, bb1 + off, al, at, ar, ab);
            if (v > best || (v == best && c < bestc)) { best = v; bestc = c; }
        }
        for (int o = 16; o > 0; o >>= 1) {
            float v2 = __shfl_down_sync(0xffffffffu, best, o);
            int   i2 = __shfl_down_sync(0xffffffffu, bestc, o);
            if (v2 > best || (v2 == best && i2 < bestc)) { best = v2; bestc = i2; }
        }
        bestc = __shfl_sync(0xffffffffu, bestc, 0);

        const int k = bestc % 9, level = k / 3;
        const float fs = c_fs9[k];
        const int col = (int)floorf((l1 + r1) * 0.5f * fs);
        const int row = (int)floorf((t1 + bb1) * 0.5f * fs);
        const int fsl = (level == 0) ? 52 : ((level == 1) ? 26 : 13);
        const int cum = (level == 0) ? 0 : ((level == 1) ? 2704 : 3380);
        // NOTE: reference adds +level (not k%3) — replicate exactly.
        const int midx = (cum + row * fsl + col) * 3 + level;
        const float* pm = pb + (size_t)midx * 25;

        float contrib = 0.f;
        if (lane < NCLS) {
            contrib = bce01(pm[5 + lane], (slb[i] - 1) == lane);
        } else if (lane == NCLS) {
            contrib = focal1(pm[4]);
        } else if (lane == NCLS + 1) {
            float fa = (float)fsl;
            float acx = ancs[midx * 4 + 0], acy = ancs[midx * 4 + 1];
            float aw  = ancs[midx * 4 + 2], ah  = ancs[midx * 4 + 3];
            float px = sigm(pm[0]) / fa + acx;
            float py = sigm(pm[1]) / fa + acy;
            float pw = expf(pm[2]) * aw;
            float ph = expf(pm[3]) * ah;
            float iou1 = ciouf(l1, t1, r1, bb1,
                               px - pw * 0.5f, py - ph * 0.5f,
                               px + pw * 0.5f, py + ph * 0.5f);
            float gw = r1 - l1, gh = bb1 - t1;
            contrib = (2.f - gw * gh) * (1.f - iou1);
        }
        for (int o = 16; o > 0; o >>= 1)
            contrib += __shfl_down_sync(0xffffffffu, contrib, o);
        if (lane == 0) wacc += contrib;
    }
    if (lane == 0) wsum[warp] = wacc;
    __syncthreads();
    if (tid == 0) {
        float s = 0.f;
        for (int w = 0; w < 16; w++) s += wsum[w];
        g_pos[b] = s;   // l_cls + l_iou + l_conf_pos (undivided)
    }
}

// =====================================================================
// Kernel 2: per-anchor OHEM key (ORDERING ONLY -> fast approx math is
// safe). Thread = (image, anchor): decode pred, max CIoU vs 50 GT
// boxes, masked -> order-preserving uint32.
// =====================================================================
__global__ void __launch_bounds__(256)
k_neg_keys(const float* __restrict__ p, const float* __restrict__ boxes,
           const float* __restrict__ ancs)
{
    const int b = blockIdx.y;
    const int a = blockIdx.x * blockDim.x + threadIdx.x;

    __shared__ float4 sA[NBOX];   // l,t,r,b
    __shared__ float4 sB[NBOX];   // l+r, t+b, area+EPS, atan(w/h)
    if (threadIdx.x < NBOX) {
        const float* bp = boxes + (size_t)(b * NBOX + threadIdx.x) * 4;
        float l = bp[0], t = bp[1], r = bp[2], bb = bp[3];
        sA[threadIdx.x] = make_float4(l, t, r, bb);
        sB[threadIdx.x] = make_float4(l + r, t + bb,
                                      (r - l) * (bb - t) + EPSF,
                                      atanf((r - l) / ((bb - t) + EPSF)));
    }
    __syncthreads();
    if (a >= A_TOT) return;

    const float* pp = p + ((size_t)b * A_TOT + a) * 25;
    const int level = (a < 8112) ? 0 : ((a < 10140) ? 1 : 2);
    const float rfa = (level == 0) ? (1.f/52.f) : ((level == 1) ? (1.f/26.f) : (1.f/13.f));
    float p0 = pp[0], p1 = pp[1], p2 = pp[2], p3 = pp[3];
    const float4 anc = __ldg((const float4*)(ancs) + a);   // rows are 16B-aligned
    float sx = __fdividef(1.f, 1.f + __expf(-p0));
    float sy = __fdividef(1.f, 1.f + __expf(-p1));
    float px = sx * rfa + anc.x;
    float py = sy * rfa + anc.y;
    float pw = __expf(p2) * anc.z;
    float ph = __expf(p3) * anc.w;
    float l1 = px - pw * 0.5f, t1 = py - ph * 0.5f;
    float r1 = px + pw * 0.5f, b1 = py + ph * 0.5f;
    float area1 = pw * ph;
    float atan1 = atanf(__fdividef(pw, ph + EPSF));
    float s1x = l1 + r1, s1y = t1 + b1;

    float mx = -1e30f;
    #pragma unroll 10
    for (int j = 0; j < NBOX; j++) {
        float4 bx = sA[j];
        float4 ex = sB[j];
        float iw = fmaxf(fminf(r1, bx.z) - fmaxf(l1, bx.x), 0.f);
        float ih = fmaxf(fminf(b1, bx.w) - fmaxf(t1, bx.y), 0.f);
        float inter = iw * ih;
        float uni = area1 + ex.z - inter;        // ex.z = area2+eps
        float iou = __fdividef(inter, uni);
        float cw = fmaxf(r1, bx.z) - fminf(l1, bx.x);
        float ch = fmaxf(b1, bx.w) - fminf(t1, bx.y);
        float c2 = fmaf(cw, cw, ch * ch) + EPSF;
        float dx = s1x - ex.x, dy = s1y - ex.y;
        float rho2 = 0.25f * fmaf(dx, dx, dy * dy);
        float dv = ex.w - atan1;                 // symmetric in square
        float v = FOURPI2 * dv * dv;
        float ci = iou - __fdividef(rho2, c2)
                       - __fdividef(v * v, 1.f - iou + v + EPSF);
        mx = fmaxf(mx, ci);
    }
    float masked = (mx < 0.5f) ? mx : __int_as_float(0x7f800000); // +inf
    uint32_t u = __float_as_uint(masked);
    uint32_t key = (u & 0x80000000u) ? ~u : (u | 0x80000000u);
    g_keys[b * A_TOT + a] = key;
}

// =====================================================================
// Kernel 3: per-image radix-select of the 1000 smallest keys (exact
// top_k tie semantics: equal value -> lower index) + sum focal(conf,0).
// One block per image, keys resident in shared memory.
// Static smem budget: 42588 (sk) + 1024 (hist) + 256 (eqIdx) + 64 (red)
// + scalars ≈ 43.9 KB < 48 KB.
// =====================================================================
#define EQ_CAP 64
__global__ void __launch_bounds__(512)
k_select_neg(const float* __restrict__ p)
{
    const int b = blockIdx.x;
    __shared__ uint32_t sk[A_TOT];
    __shared__ unsigned int hist[256];
    __shared__ uint32_t s_prefix;
    __shared__ int s_k;
    __shared__ int eqIdx[EQ_CAP];
    __shared__ int eqCnt;
    __shared__ float red[16];

    const int tid = threadIdx.x, NT = 512;
    const int warp = tid >> 5, lane = tid & 31;
    for (int i = tid; i < A_TOT; i += NT) sk[i] = g_keys[b * A_TOT + i];
    if (tid == 0) { s_prefix = 0u; s_k = NUM_NEG; eqCnt = 0; }
    __syncthreads();

    for (int pass = 0; pass < 4; pass++) {
        const int shift = 24 - 8 * pass;
        const uint32_t himask = (pass == 0) ? 0u : (0xFFFFFFFFu << (shift + 8));
        if (tid < 256) hist[tid] = 0u;
        __syncthreads();
        const uint32_t pref = s_prefix;
        for (int i = tid; i < A_TOT; i += NT) {
            uint32_t key = sk[i];
            if ((key & himask) == pref)
                atomicAdd(&hist[(key >> shift) & 255u], 1u);
        }
        __syncthreads();
        if (tid == 0) {
            int k = s_k, cum = 0, d = 0;
            for (; d < 255; d++) {
                if (cum + (int)hist[d] >= k) break;
                cum += (int)hist[d];
            }
            s_prefix = pref | ((uint32_t)d << shift);
            s_k = k - cum;
        }
        __syncthreads();
    }
    const uint32_t V = s_prefix;
    const int kRem = s_k;

    // collect indices of keys == V (rank among equals must follow index order)
    for (int i = tid; i < A_TOT; i += NT) {
        if (sk[i] == V) {
            int pos = atomicAdd(&eqCnt, 1);
            if (pos < EQ_CAP) eqIdx[pos] = i;
        }
    }
    __syncthreads();
    const int nEq = eqCnt;

    float part = 0.f;
    for (int i = tid; i < A_TOT; i += NT) {
        uint32_t key = sk[i];
        bool take = false;
        if (key < V) take = true;
        else if (key == V) {
            int rank = 0;
            if (nEq <= EQ_CAP) {
                for (int e = 0; e < nEq; e++) rank += (eqIdx[e] < i);
            } else {
                // pathological mass-tie fallback: exact O(i) scan
                for (int j = 0; j < i; j++) rank += (sk[j] == V);
            }
            take = (rank < kRem);
        }
        if (take) part += focal0(p[((size_t)b * A_TOT + i) * 25 + 4]);
    }
    // warp-shuffle reduction, then cross-warp via red[16]
    for (int o = 16; o > 0; o >>= 1)
        part += __shfl_down_sync(0xffffffffu, part, o);
    if (lane == 0) red[warp] = part;
    __syncthreads();
    if (tid == 0) {
        float s = 0.f;
        for (int w = 0; w < 16; w++) s += red[w];
        g_neg[b] = s;
    }
}

// =====================================================================
// Kernel 4: combine -> scalar. out = mean_b( pos_b/50 + neg_b )
// =====================================================================
__global__ void k_final(float* __restrict__ out)
{
    if (threadIdx.x == 0 && blockIdx.x == 0) {
        float s = 0.f;
        for (int b = 0; b < B_IMG; b++)
            s += g_pos[b] * (1.f / (float)NBOX) + g_neg[b];
        out[0] = s * (1.f / (float)B_IMG);
    }
}

extern "C" void kernel_launch(void* const* d_in, const int* in_sizes, int n_in,
                              void* d_out, int out_size)
{
    const float* p      = (const float*)d_in[0];   // [32,10647,25]
    const float* boxes  = (const float*)d_in[1];   // [32,50,4] ltrb
    const int*   labels = (const int*)d_in[2];     // [32,50]
    const float* ancs   = (const float*)d_in[3];   // [10647,4] xywh
    float* out = (float*)d_out;

    k_match_pos<<<B_IMG, 512>>>(p, boxes, labels, ancs);

    dim3 gB((A_TOT + 255) / 256, B_IMG);
    k_neg_keys<<<gB, 256>>>(p, boxes, ancs);

    k_select_neg<<<B_IMG, 512>>>(p);

    k_final<<<1, 32>>>(out);
}

// round 8
// speedup vs baseline: 2.6543x; 1.4059x over previous
#include <cuda_runtime.h>
#include <math.h>
#include <stdint.h>

#define B_IMG   32
#define NBOX    50
#define NCLS    20
#define A_TOT   10647
#define NUM_NEG 1000
#define EPSF    1e-7f
#define FOURPI2 0.4052847345693511f   // 4/pi^2
#define KEY_BLOCKS 42                 // ceil(10647/256)

// ---- scratch (no allocations allowed) ----
__device__ float    g_pos[B_IMG];
__device__ float    g_neg[B_IMG];
__device__ uint32_t g_keys[B_IMG * A_TOT];
__device__ int      g_cnt = 0;        // last-block counter (self-resetting)

__constant__ float c_asc[9][2] = {
    {10.f/416.f,13.f/416.f},{16.f/416.f,30.f/416.f},{33.f/416.f,23.f/416.f},
    {30.f/416.f,61.f/416.f},{62.f/416.f,45.f/416.f},{59.f/416.f,119.f/416.f},
    {116.f/416.f,90.f/416.f},{156.f/416.f,198.f/416.f},{373.f/416.f,326.f/416.f}};
__constant__ float c_fs9[9] = {52.f,52.f,52.f,26.f,26.f,26.f,13.f,13.f,13.f};

// ---- precise math helpers (value-bearing paths) ----
__device__ __forceinline__ float softplusf(float x) {
    return fmaxf(x, 0.f) + log1pf(expf(-fabsf(x)));
}
__device__ __forceinline__ float sigm(float x) { return 1.f / (1.f + expf(-x)); }
__device__ __forceinline__ float focal0(float x) {           // focal(x, t=0)
    float pr = sigm(x);
    return softplusf(x) * 0.75f * pr * pr;
}
__device__ __forceinline__ float focal1(float x) {           // focal(x, t=1)
    float pr = sigm(x); float q = 1.f - pr;
    return softplusf(-x) * 0.25f * q * q;
}
__device__ __forceinline__ float bce01(float x, bool t1) {
    return t1 ? softplusf(-x) : softplusf(x);
}

// Full-precision CIoU on two ltrb boxes (matches reference formula)
__device__ __forceinline__ float ciouf(float l1, float t1, float r1, float b1,
                                       float l2, float t2, float r2, float b2) {
    float iw = fminf(r1, r2) - fmaxf(l1, l2); iw = fmaxf(iw, 0.f);
    float ih = fminf(b1, b2) - fmaxf(t1, t2); ih = fmaxf(ih, 0.f);
    float inter = iw * ih;
    float w1 = r1 - l1, h1 = b1 - t1;
    float w2 = r2 - l2, h2 = b2 - t2;
    float uni = w1 * h1 + w2 * h2 - inter + EPSF;
    float iou = inter / uni;
    float cw = fmaxf(r1, r2) - fminf(l1, l2);
    float ch = fmaxf(b1, b2) - fminf(t1, t2);
    float c2 = cw * cw + ch * ch + EPSF;
    float dx = (l1 + r1) - (l2 + r2);
    float dy = (t1 + b1) - (t2 + b2);
    float rho2 = 0.25f * (dx * dx + dy * dy);
    float dv = atanf(w1 / (h1 + EPSF)) - atanf(w2 / (h2 + EPSF));
    float v = FOURPI2 * dv * dv;
    float al = v / (1.f - iou + v + EPSF);
    return iou - rho2 / c2 - al * v;
}

// =====================================================================
// Kernel 1 (fused): per-anchor OHEM keys for all anchors; block x==0 of
// each image additionally does anchor matching + positive losses.
//
// Matching note: the reference's +ids offset trick guarantees each box's
// argmax over the nb*9 candidate matrix falls within its OWN 9
// candidates (cross-j CIoU <= ~-0.6 vs own-cell >= ~-0.3), and CIoU is
// translation-invariant, so argmax over the box's 9 candidates (lowest
// index on ties) is exactly the reference argmax.
// =====================================================================
__global__ void __launch_bounds__(256)
k_keys_match(const float* __restrict__ p, const float* __restrict__ boxes,
             const int* __restrict__ labels, const float* __restrict__ ancs)
{
    const int b = blockIdx.y;
    const int tid = threadIdx.x, wid = tid >> 5, lane = tid & 31;
    const int a = blockIdx.x * 256 + tid;

    __shared__ float4 sA[NBOX];   // l,t,r,b
    __shared__ float4 sB[NBOX];   // l+r, t+b, area+EPS, atan(w/h)
    __shared__ float  wsum[8];
    if (tid < NBOX) {
        const float* bp = boxes + (size_t)(b * NBOX + tid) * 4;
        float l = bp[0], t = bp[1], r = bp[2], bb = bp[3];
        sA[tid] = make_float4(l, t, r, bb);
        sB[tid] = make_float4(l + r, t + bb,
                              (r - l) * (bb - t) + EPSF,
                              atanf((r - l) / ((bb - t) + EPSF)));
    }
    __syncthreads();

    // ---------------- per-anchor key (ordering only -> fast math) -------------
    if (a < A_TOT) {
        const float* pp = p + ((size_t)b * A_TOT + a) * 25;
        const int level = (a < 8112) ? 0 : ((a < 10140) ? 1 : 2);
        const float rfa = (level == 0) ? (1.f/52.f) : ((level == 1) ? (1.f/26.f) : (1.f/13.f));
        float p0 = pp[0], p1 = pp[1], p2 = pp[2], p3 = pp[3];
        const float4 anc = __ldg((const float4*)(ancs) + a);
        float sx = __fdividef(1.f, 1.f + __expf(-p0));
        float sy = __fdividef(1.f, 1.f + __expf(-p1));
        float px = sx * rfa + anc.x;
        float py = sy * rfa + anc.y;
        float pw = __expf(p2) * anc.z;
        float ph = __expf(p3) * anc.w;
        float l1 = px - pw * 0.5f, t1 = py - ph * 0.5f;
        float r1 = px + pw * 0.5f, b1 = py + ph * 0.5f;
        float area1 = pw * ph;
        float atan1 = atanf(__fdividef(pw, ph + EPSF));
        float s1x = l1 + r1, s1y = t1 + b1;

        float mx = -1e30f;
        #pragma unroll 10
        for (int j = 0; j < NBOX; j++) {
            float4 bx = sA[j];
            float4 ex = sB[j];
            float iw = fmaxf(fminf(r1, bx.z) - fmaxf(l1, bx.x), 0.f);
            float ih = fmaxf(fminf(b1, bx.w) - fmaxf(t1, bx.y), 0.f);
            float inter = iw * ih;
            float uni = area1 + ex.z - inter;        // ex.z = area2+eps
            float iou = __fdividef(inter, uni);
            float cw = fmaxf(r1, bx.z) - fminf(l1, bx.x);
            float ch = fmaxf(b1, bx.w) - fminf(t1, bx.y);
            float c2 = fmaf(cw, cw, ch * ch) + EPSF;
            float dx = s1x - ex.x, dy = s1y - ex.y;
            float rho2 = 0.25f * fmaf(dx, dx, dy * dy);
            float dv = ex.w - atan1;                 // symmetric in square
            float v = FOURPI2 * dv * dv;
            float ci = iou - __fdividef(rho2, c2)
                           - __fdividef(v * v, 1.f - iou + v + EPSF);
            mx = fmaxf(mx, ci);
        }
        float masked = (mx < 0.5f) ? mx : __int_as_float(0x7f800000); // +inf
        uint32_t u = __float_as_uint(masked);
        uint32_t key = (u & 0x80000000u) ? ~u : (u | 0x80000000u);
        g_keys[b * A_TOT + a] = key;
    }

    // ---------------- matching + positive losses (block x == 0 only) ---------
    if (blockIdx.x != 0) return;
    const float* pb = p + (size_t)b * A_TOT * 25;
    float wacc = 0.f;

    for (int i = wid; i < NBOX; i += 8) {
        const float4 bx = sA[i];
        const float l1 = bx.x, t1 = bx.y, r1 = bx.z, bb1 = bx.w;

        // lanes 0..8 each evaluate one of the 9 own-cell candidates (precise)
        float best = -1e30f; int bestm = 1 << 30;
        if (lane < 9) {
            const int m = lane;
            float fs = c_fs9[m];
            float ax = floorf((l1 + r1) * 0.5f * fs) / fs;
            float ay = floorf((t1 + bb1) * 0.5f * fs) / fs;
            float aw = c_asc[m][0], ah = c_asc[m][1];
            best = ciouf(l1, t1, r1, bb1,
                         ax - aw * 0.5f, ay - ah * 0.5f,
                         ax + aw * 0.5f, ay + ah * 0.5f);
            bestm = m;
        }
        for (int o = 8; o > 0; o >>= 1) {
            float v2 = __shfl_down_sync(0xffffffffu, best, o);
            int   m2 = __shfl_down_sync(0xffffffffu, bestm, o);
            if (v2 > best || (v2 == best && m2 < bestm)) { best = v2; bestm = m2; }
        }
        const int k = __shfl_sync(0xffffffffu, bestm, 0);

        const int level = k / 3;
        const float fs = c_fs9[k];
        const int col = (int)floorf((l1 + r1) * 0.5f * fs);
        const int row = (int)floorf((t1 + bb1) * 0.5f * fs);
        const int fsl = (level == 0) ? 52 : ((level == 1) ? 26 : 13);
        const int cum = (level == 0) ? 0 : ((level == 1) ? 2704 : 3380);
        // NOTE: reference adds +level (not k%3) — replicate exactly.
        const int midx = (cum + row * fsl + col) * 3 + level;
        const float* pm = pb + (size_t)midx * 25;

        float contrib = 0.f;
        if (lane < NCLS) {
            contrib = bce01(pm[5 + lane], (labels[b * NBOX + i] - 1) == lane);
        } else if (lane == NCLS) {
            contrib = focal1(pm[4]);
        } else if (lane == NCLS + 1) {
            float fa = (float)fsl;
            float acx = ancs[midx * 4 + 0], acy = ancs[midx * 4 + 1];
            float aw  = ancs[midx * 4 + 2], ah  = ancs[midx * 4 + 3];
            float px = sigm(pm[0]) / fa + acx;
            float py = sigm(pm[1]) / fa + acy;
            float pw = expf(pm[2]) * aw;
            float ph = expf(pm[3]) * ah;
            float iou1 = ciouf(l1, t1, r1, bb1,
                               px - pw * 0.5f, py - ph * 0.5f,
                               px + pw * 0.5f, py + ph * 0.5f);
            float gw = r1 - l1, gh = bb1 - t1;
            contrib = (2.f - gw * gh) * (1.f - iou1);
        }
        for (int o = 16; o > 0; o >>= 1)
            contrib += __shfl_down_sync(0xffffffffu, contrib, o);
        if (lane == 0) wacc += contrib;
    }
    if (lane == 0) wsum[wid] = wacc;
    __syncthreads();
    if (tid == 0) {
        float s = 0.f;
        for (int w = 0; w < 8; w++) s += wsum[w];
        g_pos[b] = s;   // l_cls + l_iou + l_conf_pos (undivided)
    }
}

// =====================================================================
// Kernel 2: per-image radix-select of the 1000 smallest keys (exact
// top_k tie semantics) + sum focal(conf,0); last block folds the final
// scalar. Smem: 42588 (sk) + 1024 (hist) + 256 (eqIdx) + 64 (red) < 48K.
// =====================================================================
#define EQ_CAP 64
__global__ void __launch_bounds__(512)
k_select_neg(const float* __restrict__ p, float* __restrict__ out)
{
    const int b = blockIdx.x;
    __shared__ uint32_t sk[A_TOT];
    __shared__ unsigned int hist[256];
    __shared__ uint32_t s_prefix;
    __shared__ int s_k;
    __shared__ int eqIdx[EQ_CAP];
    __shared__ int eqCnt;
    __shared__ float red[16];
    __shared__ int s_last;

    const int tid = threadIdx.x, NT = 512;
    const int warp = tid >> 5, lane = tid & 31;
    for (int i = tid; i < A_TOT; i += NT) sk[i] = g_keys[b * A_TOT + i];
    if (tid == 0) { s_prefix = 0u; s_k = NUM_NEG; eqCnt = 0; }
    __syncthreads();

    for (int pass = 0; pass < 4; pass++) {
        const int shift = 24 - 8 * pass;
        const uint32_t himask = (pass == 0) ? 0u : (0xFFFFFFFFu << (shift + 8));
        if (tid < 256) hist[tid] = 0u;
        __syncthreads();
        const uint32_t pref = s_prefix;
        for (int i = tid; i < A_TOT; i += NT) {
            uint32_t key = sk[i];
            if ((key & himask) == pref)
                atomicAdd(&hist[(key >> shift) & 255u], 1u);
        }
        __syncthreads();
        if (tid == 0) {
            int k = s_k, cum = 0, d = 0;
            for (; d < 255; d++) {
                if (cum + (int)hist[d] >= k) break;
                cum += (int)hist[d];
            }
            s_prefix = pref | ((uint32_t)d << shift);
            s_k = k - cum;
        }
        __syncthreads();
    }
    const uint32_t V = s_prefix;
    const int kRem = s_k;

    for (int i = tid; i < A_TOT; i += NT) {
        if (sk[i] == V) {
            int pos = atomicAdd(&eqCnt, 1);
            if (pos < EQ_CAP) eqIdx[pos] = i;
        }
    }
    __syncthreads();
    const int nEq = eqCnt;

    float part = 0.f;
    for (int i = tid; i < A_TOT; i += NT) {
        uint32_t key = sk[i];
        bool take = false;
        if (key < V) take = true;
        else if (key == V) {
            int rank = 0;
            if (nEq <= EQ_CAP) {
                for (int e = 0; e < nEq; e++) rank += (eqIdx[e] < i);
            } else {
                for (int j = 0; j < i; j++) rank += (sk[j] == V);
            }
            take = (rank < kRem);
        }
        if (take) part += focal0(p[((size_t)b * A_TOT + i) * 25 + 4]);
    }
    for (int o = 16; o > 0; o >>= 1)
        part += __shfl_down_sync(0xffffffffu, part, o);
    if (lane == 0) red[warp] = part;
    __syncthreads();
    if (tid == 0) {
        float s = 0.f;
        for (int w = 0; w < 16; w++) s += red[w];
        g_neg[b] = s;
        __threadfence();
        int t = atomicAdd(&g_cnt, 1);
        s_last = (t == B_IMG - 1);
    }
    __syncthreads();
    if (s_last && tid == 0) {
        float s = 0.f;
        for (int bb = 0; bb < B_IMG; bb++)
            s += g_pos[bb] * (1.f / (float)NBOX) + g_neg[bb];
        out[0] = s * (1.f / (float)B_IMG);
        g_cnt = 0;   // self-reset for deterministic graph replays
    }
}

extern "C" void kernel_launch(void* const* d_in, const int* in_sizes, int n_in,
                              void* d_out, int out_size)
{
    const float* p      = (const float*)d_in[0];   // [32,10647,25]
    const float* boxes  = (const float*)d_in[1];   // [32,50,4] ltrb
    const int*   labels = (const int*)d_in[2];     // [32,50]
    const float* ancs   = (const float*)d_in[3];   // [10647,4] xywh
    float* out = (float*)d_out;

    dim3 g1(KEY_BLOCKS, B_IMG);
    k_keys_match<<<g1, 256>>>(p, boxes, labels, ancs);

    k_select_neg<<<B_IMG, 512>>>(p, out);
}

// round 9
// speedup vs baseline: 3.5458x; 1.3359x over previous
#include <cuda_runtime.h>
#include <math.h>
#include <stdint.h>

#define B_IMG   32
#define NBOX    50
#define NCLS    20
#define A_TOT   10647
#define NUM_NEG 1000
#define EPSF    1e-7f
#define FOURPI2 0.4052847345693511f   // 4/pi^2
#define HALF_A  5376                  // 21*256 ; thread covers a and a+HALF_A
#define KEY_BLOCKS 21                 // ceil(5376/256)

// ---- scratch (no allocations allowed) ----
__device__ float    g_pos[B_IMG];
__device__ float    g_neg[B_IMG];
__device__ uint32_t g_keys[B_IMG * A_TOT];
__device__ int      g_cnt = 0;        // last-block counter (self-resetting)

__constant__ float c_asc[9][2] = {
    {10.f/416.f,13.f/416.f},{16.f/416.f,30.f/416.f},{33.f/416.f,23.f/416.f},
    {30.f/416.f,61.f/416.f},{62.f/416.f,45.f/416.f},{59.f/416.f,119.f/416.f},
    {116.f/416.f,90.f/416.f},{156.f/416.f,198.f/416.f},{373.f/416.f,326.f/416.f}};
__constant__ float c_fs9[9] = {52.f,52.f,52.f,26.f,26.f,26.f,13.f,13.f,13.f};

// ---- precise math helpers (value-bearing paths) ----
__device__ __forceinline__ float softplusf(float x) {
    return fmaxf(x, 0.f) + log1pf(expf(-fabsf(x)));
}
__device__ __forceinline__ float sigm(float x) { return 1.f / (1.f + expf(-x)); }
__device__ __forceinline__ float focal0(float x) {           // focal(x, t=0)
    float pr = sigm(x);
    return softplusf(x) * 0.75f * pr * pr;
}
__device__ __forceinline__ float focal1(float x) {           // focal(x, t=1)
    float pr = sigm(x); float q = 1.f - pr;
    return softplusf(-x) * 0.25f * q * q;
}
__device__ __forceinline__ float bce01(float x, bool t1) {
    return t1 ? softplusf(-x) : softplusf(x);
}

// Full-precision CIoU on two ltrb boxes (matches reference formula)
__device__ __forceinline__ float ciouf(float l1, float t1, float r1, float b1,
                                       float l2, float t2, float r2, float b2) {
    float iw = fminf(r1, r2) - fmaxf(l1, l2); iw = fmaxf(iw, 0.f);
    float ih = fminf(b1, b2) - fmaxf(t1, t2); ih = fmaxf(ih, 0.f);
    float inter = iw * ih;
    float w1 = r1 - l1, h1 = b1 - t1;
    float w2 = r2 - l2, h2 = b2 - t2;
    float uni = w1 * h1 + w2 * h2 - inter + EPSF;
    float iou = inter / uni;
    float cw = fmaxf(r1, r2) - fminf(l1, l2);
    float ch = fmaxf(b1, b2) - fminf(t1, t2);
    float c2 = cw * cw + ch * ch + EPSF;
    float dx = (l1 + r1) - (l2 + r2);
    float dy = (t1 + b1) - (t2 + b2);
    float rho2 = 0.25f * (dx * dx + dy * dy);
    float dv = atanf(w1 / (h1 + EPSF)) - atanf(w2 / (h2 + EPSF));
    float v = FOURPI2 * dv * dv;
    float al = v / (1.f - iou + v + EPSF);
    return iou - rho2 / c2 - al * v;
}

// ---- fast CIoU chain state for the OHEM key path (ordering only) ----
struct AncBox {
    float l, t, r, b, px, py, pw, ph, area, atanv, mx;
};

__device__ __forceinline__ void anc_decode(AncBox& s, const float* __restrict__ p,
                                           const float* __restrict__ ancs,
                                           int b, int a)
{
    const float* pp = p + ((size_t)b * A_TOT + a) * 25;
    const int level = (a < 8112) ? 0 : ((a < 10140) ? 1 : 2);
    const float rfa = (level == 0) ? (1.f/52.f) : ((level == 1) ? (1.f/26.f) : (1.f/13.f));
    const float4 anc = __ldg((const float4*)(ancs) + a);
    float sx = __fdividef(1.f, 1.f + __expf(-pp[0]));
    float sy = __fdividef(1.f, 1.f + __expf(-pp[1]));
    s.px = sx * rfa + anc.x;
    s.py = sy * rfa + anc.y;
    s.pw = __expf(pp[2]) * anc.z;
    s.ph = __expf(pp[3]) * anc.w;
    s.l = s.px - s.pw * 0.5f; s.t = s.py - s.ph * 0.5f;
    s.r = s.px + s.pw * 0.5f; s.b = s.py + s.ph * 0.5f;
    s.area = s.pw * s.ph;
    s.atanv = atanf(__fdividef(s.pw, s.ph + EPSF));
    s.mx = -1e30f;
}

// one fast CIoU step vs box j (bx = ltrb, ex = {cx, cy, area+eps, atan}, wh = {w,h})
__device__ __forceinline__ void anc_step(AncBox& s, float4 bx, float4 ex, float2 wh)
{
    float iwu = fminf(s.r, bx.z) - fmaxf(s.l, bx.x);
    float ihu = fminf(s.b, bx.w) - fmaxf(s.t, bx.y);
    float inter = fmaxf(iwu, 0.f) * fmaxf(ihu, 0.f);
    float uni = s.area + ex.z - inter;                 // ex.z = area2+eps
    float iou = __fdividef(inter, uni);
    float cw = (s.pw + wh.x) - iwu;                    // max-min identity
    float ch = (s.ph + wh.y) - ihu;
    float c2 = fmaf(cw, cw, fmaf(ch, ch, EPSF));
    float dx = s.px - ex.x, dy = s.py - ex.y;          // centers -> 0.25 folded
    float rho2 = fmaf(dx, dx, dy * dy);
    float dv = ex.w - s.atanv;
    float v = FOURPI2 * (dv * dv);
    float ci = iou - __fdividef(rho2, c2)
                   - __fdividef(v * v, 1.f - iou + v + EPSF);
    s.mx = fmaxf(s.mx, ci);
}

__device__ __forceinline__ uint32_t key_of(float mx)
{
    float masked = (mx < 0.5f) ? mx : __int_as_float(0x7f800000); // +inf
    uint32_t u = __float_as_uint(masked);
    return (u & 0x80000000u) ? ~u : (u | 0x80000000u);
}

// =====================================================================
// Kernel 1 (fused): per-anchor OHEM keys (2 anchors per thread);
// block x==0 of each image also does anchor matching + positive losses.
//
// Matching note: the reference's +ids offset trick guarantees each box's
// argmax over the nb*9 candidate matrix falls within its OWN 9
// candidates, and CIoU is translation-invariant -> argmax over the 9
// own-cell candidates (lowest index on ties) equals the reference.
// =====================================================================
__global__ void __launch_bounds__(256)
k_keys_match(const float* __restrict__ p, const float* __restrict__ boxes,
             const int* __restrict__ labels, const float* __restrict__ ancs)
{
    const int b = blockIdx.y;
    const int tid = threadIdx.x, wid = tid >> 5, lane = tid & 31;

    __shared__ float4 sA[NBOX];   // l,t,r,b
    __shared__ float4 sB[NBOX];   // cx, cy, area+eps, atan(w/h)
    __shared__ float2 sC[NBOX];   // w, h
    __shared__ float  wsum[8];
    if (tid < NBOX) {
        const float* bp = boxes + (size_t)(b * NBOX + tid) * 4;
        float l = bp[0], t = bp[1], r = bp[2], bb = bp[3];
        float w = r - l, h = bb - t;
        sA[tid] = make_float4(l, t, r, bb);
        sB[tid] = make_float4((l + r) * 0.5f, (t + bb) * 0.5f,
                              w * h + EPSF,
                              atanf(w / (h + EPSF)));
        sC[tid] = make_float2(w, h);
    }
    __syncthreads();

    // ---------------- per-anchor keys: 2 chains per thread -------------------
    {
        const int a0 = blockIdx.x * 256 + tid;       // [0, HALF_A)
        const int a1 = a0 + HALF_A;                  // [HALF_A, 2*HALF_A)
        const bool do1 = (a1 < A_TOT);
        AncBox s0, s1;
        anc_decode(s0, p, ancs, b, a0);
        anc_decode(s1, p, ancs, b, do1 ? a1 : 0);

        #pragma unroll 5
        for (int j = 0; j < NBOX; j++) {
            float4 bx = sA[j];
            float4 ex = sB[j];
            float2 wh = sC[j];
            anc_step(s0, bx, ex, wh);
            anc_step(s1, bx, ex, wh);
        }
        g_keys[b * A_TOT + a0] = key_of(s0.mx);
        if (do1) g_keys[b * A_TOT + a1] = key_of(s1.mx);
    }

    // ---------------- matching + positive losses (block x == 0 only) ---------
    if (blockIdx.x != 0) return;
    const float* pb = p + (size_t)b * A_TOT * 25;
    float wacc = 0.f;

    for (int i = wid; i < NBOX; i += 8) {
        const float4 bx = sA[i];
        const float l1 = bx.x, t1 = bx.y, r1 = bx.z, bb1 = bx.w;

        // lanes 0..8 each evaluate one of the 9 own-cell candidates (precise)
        float best = -1e30f; int bestm = 1 << 30;
        if (lane < 9) {
            const int m = lane;
            float fs = c_fs9[m];
            float ax = floorf((l1 + r1) * 0.5f * fs) / fs;
            float ay = floorf((t1 + bb1) * 0.5f * fs) / fs;
            float aw = c_asc[m][0], ah = c_asc[m][1];
            best = ciouf(l1, t1, r1, bb1,
                         ax - aw * 0.5f, ay - ah * 0.5f,
                         ax + aw * 0.5f, ay + ah * 0.5f);
            bestm = m;
        }
        for (int o = 8; o > 0; o >>= 1) {
            float v2 = __shfl_down_sync(0xffffffffu, best, o);
            int   m2 = __shfl_down_sync(0xffffffffu, bestm, o);
            if (v2 > best || (v2 == best && m2 < bestm)) { best = v2; bestm = m2; }
        }
        const int k = __shfl_sync(0xffffffffu, bestm, 0);

        const int level = k / 3;
        const float fs = c_fs9[k];
        const int col = (int)floorf((l1 + r1) * 0.5f * fs);
        const int row = (int)floorf((t1 + bb1) * 0.5f * fs);
        const int fsl = (level == 0) ? 52 : ((level == 1) ? 26 : 13);
        const int cum = (level == 0) ? 0 : ((level == 1) ? 2704 : 3380);
        // NOTE: reference adds +level (not k%3) — replicate exactly.
        const int midx = (cum + row * fsl + col) * 3 + level;
        const float* pm = pb + (size_t)midx * 25;

        float contrib = 0.f;
        if (lane < NCLS) {
            contrib = bce01(pm[5 + lane], (labels[b * NBOX + i] - 1) == lane);
        } else if (lane == NCLS) {
            contrib = focal1(pm[4]);
        } else if (lane == NCLS + 1) {
            float fa = (float)fsl;
            float acx = ancs[midx * 4 + 0], acy = ancs[midx * 4 + 1];
            float aw  = ancs[midx * 4 + 2], ah  = ancs[midx * 4 + 3];
            float px = sigm(pm[0]) / fa + acx;
            float py = sigm(pm[1]) / fa + acy;
            float pw = expf(pm[2]) * aw;
            float ph = expf(pm[3]) * ah;
            float iou1 = ciouf(l1, t1, r1, bb1,
                               px - pw * 0.5f, py - ph * 0.5f,
                               px + pw * 0.5f, py + ph * 0.5f);
            float gw = r1 - l1, gh = bb1 - t1;
            contrib = (2.f - gw * gh) * (1.f - iou1);
        }
        for (int o = 16; o > 0; o >>= 1)
            contrib += __shfl_down_sync(0xffffffffu, contrib, o);
        if (lane == 0) wacc += contrib;
    }
    if (lane == 0) wsum[wid] = wacc;
    __syncthreads();
    if (tid == 0) {
        float s = 0.f;
        for (int w = 0; w < 8; w++) s += wsum[w];
        g_pos[b] = s;   // l_cls + l_iou + l_conf_pos (undivided)
    }
}

// =====================================================================
// Kernel 2: per-image radix-select of the 1000 smallest keys (exact
// top_k tie semantics) + sum focal(conf,0); last block folds the final
// scalar. Digit selection uses a parallel 256-bin prefix scan (the R7
// serial 255-iter scan was ~20us of one-thread latency).
// Smem: 42588 (sk) + 1024 (hist) + 32 (wscan) + 256 (eqIdx) + 128 (red)
// < 48K.
// =====================================================================
#define EQ_CAP 64
#define SEL_NT 1024
__global__ void __launch_bounds__(SEL_NT)
k_select_neg(const float* __restrict__ p, float* __restrict__ out)
{
    const int b = blockIdx.x;
    __shared__ uint32_t sk[A_TOT];
    __shared__ unsigned int hist[256];
    __shared__ unsigned int wscan[8];
    __shared__ uint32_t s_prefix;
    __shared__ int s_k;
    __shared__ int eqIdx[EQ_CAP];
    __shared__ int eqCnt;
    __shared__ float red[32];
    __shared__ int s_last;

    const int tid = threadIdx.x;
    const int warp = tid >> 5, lane = tid & 31;
    for (int i = tid; i < A_TOT; i += SEL_NT) sk[i] = g_keys[b * A_TOT + i];
    if (tid == 0) { s_prefix = 0u; s_k = NUM_NEG; eqCnt = 0; }
    __syncthreads();

    for (int pass = 0; pass < 4; pass++) {
        const int shift = 24 - 8 * pass;
        const uint32_t himask = (pass == 0) ? 0u : (0xFFFFFFFFu << (shift + 8));
        if (tid < 256) hist[tid] = 0u;
        __syncthreads();
        const uint32_t pref = s_prefix;
        const unsigned kcur = (unsigned)s_k;
        for (int i = tid; i < A_TOT; i += SEL_NT) {
            uint32_t key = sk[i];
            if ((key & himask) == pref)
                atomicAdd(&hist[(key >> shift) & 255u], 1u);
        }
        __syncthreads();
        // parallel 256-bin prefix scan (8 warps) + one-hot digit pick
        unsigned v = 0, orig = 0;
        if (tid < 256) {
            orig = hist[tid]; v = orig;
            #pragma unroll
            for (int o = 1; o < 32; o <<= 1) {
                unsigned n = __shfl_up_sync(0xffffffffu, v, o);
                if (lane >= o) v += n;
            }
            if (lane == 31) wscan[warp] = v;
        }
        __syncthreads();
        if (tid < 256) {
            unsigned off = 0;
            for (int w = 0; w < warp; w++) off += wscan[w];
            unsigned incl = v + off;
            unsigned excl = incl - orig;
            if (orig > 0u && excl < kcur && kcur <= incl) {
                s_prefix = pref | ((uint32_t)tid << shift);
                s_k = (int)(kcur - excl);
            }
        }
        __syncthreads();
    }
    const uint32_t V = s_prefix;
    const int kRem = s_k;

    // collect indices of keys == V (rank among equals follows index order)
    for (int i = tid; i < A_TOT; i += SEL_NT) {
        if (sk[i] == V) {
            int pos = atomicAdd(&eqCnt, 1);
            if (pos < EQ_CAP) eqIdx[pos] = i;
        }
    }
    __syncthreads();
    const int nEq = eqCnt;

    float part = 0.f;
    for (int i = tid; i < A_TOT; i += SEL_NT) {
        uint32_t key = sk[i];
        bool take = false;
        if (key < V) take = true;
        else if (key == V) {
            int rank = 0;
            if (nEq <= EQ_CAP) {
                for (int e = 0; e < nEq; e++) rank += (eqIdx[e] < i);
            } else {
                // pathological mass-tie fallback: exact O(i) scan
                for (int j = 0; j < i; j++) rank += (sk[j] == V);
            }
            take = (rank < kRem);
        }
        if (take) part += focal0(p[((size_t)b * A_TOT + i) * 25 + 4]);
    }
    for (int o = 16; o > 0; o >>= 1)
        part += __shfl_down_sync(0xffffffffu, part, o);
    if (lane == 0) red[warp] = part;
    __syncthreads();
    if (tid == 0) {
        float s = 0.f;
        for (int w = 0; w < 32; w++) s += red[w];
        g_neg[b] = s;
        __threadfence();
        int t = atomicAdd(&g_cnt, 1);
        s_last = (t == B_IMG - 1);
    }
    __syncthreads();
    if (s_last && tid == 0) {
        float s = 0.f;
        for (int bb = 0; bb < B_IMG; bb++)
            s += g_pos[bb] * (1.f / (float)NBOX) + g_neg[bb];
        out[0] = s * (1.f / (float)B_IMG);
        g_cnt = 0;   // self-reset for deterministic graph replays
    }
}

extern "C" void kernel_launch(void* const* d_in, const int* in_sizes, int n_in,
                              void* d_out, int out_size)
{
    const float* p      = (const float*)d_in[0];   // [32,10647,25]
    const float* boxes  = (const float*)d_in[1];   // [32,50,4] ltrb
    const int*   labels = (const int*)d_in[2];     // [32,50]
    const float* ancs   = (const float*)d_in[3];   // [10647,4] xywh
    float* out = (float*)d_out;

    dim3 g1(KEY_BLOCKS, B_IMG);
    k_keys_match<<<g1, 256>>>(p, boxes, labels, ancs);

    k_select_neg<<<B_IMG, SEL_NT>>>(p, out);
}